// round 9
// baseline (speedup 1.0000x reference)
#include <cuda_runtime.h>
#include <cuda_bf16.h>
#include <cstdint>

#define LSEQ 8192
#define FIN  1024
#define CDIM 256
#define C3   768
#define NH   8
#define DH   32
#define KS   63

__device__ float g_y[LSEQ * CDIM];
__device__ float g_qkv[LSEQ * C3];
__device__ float g_att[LSEQ * CDIM];

// Pre-rounded (tf32 RNE) weights, original [K][N] layout
__device__ float g_Wp_r[FIN * CDIM];
__device__ float g_Wq_r[CDIM * C3];
__device__ float g_Wo_r[CDIM * CDIM];

// ---------------------------------------------------------------------------
// helpers
// ---------------------------------------------------------------------------
__device__ __forceinline__ void cp16(void* smem, const void* g) {
    uint32_t s = (uint32_t)__cvta_generic_to_shared(smem);
    asm volatile("cp.async.cg.shared.global [%0], [%1], 16;\n" :: "r"(s), "l"(g));
}
__device__ __forceinline__ void cp_commit() {
    asm volatile("cp.async.commit_group;\n");
}
__device__ __forceinline__ void mma_tf32(float* d, const uint32_t* a, const uint32_t* b) {
    asm volatile(
        "mma.sync.aligned.m16n8k8.row.col.f32.tf32.tf32.f32 "
        "{%0,%1,%2,%3}, {%4,%5,%6,%7}, {%8,%9}, {%0,%1,%2,%3};\n"
        : "+f"(d[0]), "+f"(d[1]), "+f"(d[2]), "+f"(d[3])
        : "r"(a[0]), "r"(a[1]), "r"(a[2]), "r"(a[3]), "r"(b[0]), "r"(b[1]));
}
__device__ __forceinline__ uint32_t cvt_rna_tf32(float x) {
    uint32_t r;
    asm("cvt.rna.tf32.f32 %0, %1;" : "=r"(r) : "f"(x));
    return r;
}
__device__ __forceinline__ float round_tf32(float x) {
    return __uint_as_float(cvt_rna_tf32(x));
}

// ---------------------------------------------------------------------------
// Weight prep: round W to tf32 (RNE), same [K][N] layout
// ---------------------------------------------------------------------------
__global__ void prep_weights_kernel(const float* __restrict__ W,
                                    float* __restrict__ Wr, int total)
{
    int idx = blockIdx.x * blockDim.x + threadIdx.x;
    if (idx >= total) return;
    Wr[idx] = round_tf32(W[idx]);
}

// ---------------------------------------------------------------------------
// TF32 GEMM, 4-stage cp.async pipeline: C[M,N] = A @ B + bias
// BM=64 BN=128 BK=16, 256 thr (8 warps, 2m x 4n), warp tile 32x32, m16n8k8.
// CVT_A: round A inline (false if A pre-rounded). ROUND_OUT: store C tf32-rounded.
// ---------------------------------------------------------------------------
#define ASTRIDE 20
#define BSTRIDE 136
#define NSTAGE 4
#define ABYTES (64 * ASTRIDE * 4)        // 5120
#define BBYTES (16 * BSTRIDE * 4)        // 8704
#define STAGEB (ABYTES + BBYTES)         // 13824
#define GSMEM  (NSTAGE * STAGEB)         // 55296

template<bool CVT_A, bool ROUND_OUT>
__global__ __launch_bounds__(256) void gemm_tf32_kernel(
    const float* __restrict__ A, const float* __restrict__ B,
    const float* __restrict__ bias, float* __restrict__ C,
    int M, int N, int K)
{
    extern __shared__ char smem[];

    const int bm = blockIdx.y * 64;
    const int bn = blockIdx.x * 128;
    const int tid = threadIdx.x;
    const int wid = tid >> 5;
    const int lane = tid & 31;
    const int warp_m = wid & 1;     // 0..1
    const int warp_n = wid >> 1;    // 0..3
    const int r = lane >> 2;        // 0..7
    const int c = lane & 3;         // 0..3

    const int arow = tid >> 2;              // 0..63
    const int ac4  = (tid & 3) * 4;
    const int brow = tid >> 4;              // 0..15
    const int bc8  = (tid & 15) * 8;        // 0,8,..,120

    float acc[2][4][4];
    #pragma unroll
    for (int i = 0; i < 2; i++)
        #pragma unroll
        for (int j = 0; j < 4; j++)
            #pragma unroll
            for (int e = 0; e < 4; e++) acc[i][j][e] = 0.f;

    const int T = K >> 4;

    auto stage = [&](int kt, int s) {
        float* As = (float*)(smem + s * STAGEB);
        float* Bs = (float*)(smem + s * STAGEB + ABYTES);
        const int k0 = kt << 4;
        cp16(&As[arow * ASTRIDE + ac4], &A[(size_t)(bm + arow) * K + k0 + ac4]);
        cp16(&Bs[brow * BSTRIDE + bc8],     &B[(size_t)(k0 + brow) * N + bn + bc8]);
        cp16(&Bs[brow * BSTRIDE + bc8 + 4], &B[(size_t)(k0 + brow) * N + bn + bc8 + 4]);
        cp_commit();
    };

    // prologue: 3 stages in flight (T >= 3 for all our shapes)
    stage(0, 0);
    stage(1, 1);
    stage(2, 2);

    for (int i = 0; i < T; i++) {
        const int s = i & 3;
        asm volatile("cp.async.wait_group 2;\n");
        __syncthreads();

        const float* as = (const float*)(smem + s * STAGEB);
        const float* bs = (const float*)(smem + s * STAGEB + ABYTES);

        #pragma unroll
        for (int ks = 0; ks < 16; ks += 8) {
            uint32_t af[2][4], bf[4][2];
            #pragma unroll
            for (int mi = 0; mi < 2; mi++) {
                int m0 = warp_m * 32 + mi * 16;
                float a0 = as[(m0 + r)     * ASTRIDE + ks + c];
                float a1 = as[(m0 + r + 8) * ASTRIDE + ks + c];
                float a2 = as[(m0 + r)     * ASTRIDE + ks + c + 4];
                float a3 = as[(m0 + r + 8) * ASTRIDE + ks + c + 4];
                if (CVT_A) {
                    af[mi][0] = cvt_rna_tf32(a0);
                    af[mi][1] = cvt_rna_tf32(a1);
                    af[mi][2] = cvt_rna_tf32(a2);
                    af[mi][3] = cvt_rna_tf32(a3);
                } else {
                    af[mi][0] = __float_as_uint(a0);
                    af[mi][1] = __float_as_uint(a1);
                    af[mi][2] = __float_as_uint(a2);
                    af[mi][3] = __float_as_uint(a3);
                }
            }
            #pragma unroll
            for (int nj = 0; nj < 4; nj++) {
                int n0 = warp_n * 32 + nj * 8 + r;
                bf[nj][0] = __float_as_uint(bs[(ks + c)     * BSTRIDE + n0]);
                bf[nj][1] = __float_as_uint(bs[(ks + c + 4) * BSTRIDE + n0]);
            }
            #pragma unroll
            for (int mi = 0; mi < 2; mi++)
                #pragma unroll
                for (int nj = 0; nj < 4; nj++)
                    mma_tf32(acc[mi][nj], af[mi], bf[nj]);
        }

        // keep one commit-group per iteration (possibly empty) so wait_group 2 is exact
        if (i + 3 < T) stage(i + 3, (i + 3) & 3);
        else cp_commit();
    }

    #pragma unroll
    for (int mi = 0; mi < 2; mi++) {
        #pragma unroll
        for (int nj = 0; nj < 4; nj++) {
            int row = bm + warp_m * 32 + mi * 16 + r;
            int col = bn + warp_n * 32 + nj * 8 + c * 2;
            float2 bb = *(const float2*)&bias[col];
            float2 o0, o1;
            o0.x = acc[mi][nj][0] + bb.x;
            o0.y = acc[mi][nj][1] + bb.y;
            o1.x = acc[mi][nj][2] + bb.x;
            o1.y = acc[mi][nj][3] + bb.y;
            if (ROUND_OUT) {
                o0.x = round_tf32(o0.x); o0.y = round_tf32(o0.y);
                o1.x = round_tf32(o1.x); o1.y = round_tf32(o1.y);
            }
            *(float2*)&C[(size_t)row * N + col] = o0;
            *(float2*)&C[(size_t)(row + 8) * N + col] = o1;
        }
    }
}

// ---------------------------------------------------------------------------
// NATTEN-1D (round-4 structure; att stored tf32-pre-rounded for GEMM3)
// ---------------------------------------------------------------------------
#define TQ 64
#define KV 126
#define RS 36
#define PTS 12
#define PTROWS 72

__device__ __forceinline__ int win_start(int l) {
    int s = l - 31;
    if (s < 0) s = 0;
    if (s > LSEQ - KS) s = LSEQ - KS;
    return s;
}

__global__ __launch_bounds__(256) void natten_kernel(
    const float* __restrict__ qkv, float* __restrict__ out)
{
    extern __shared__ float sm[];
    float* Ks = sm;
    float* Vs = Ks + 127 * RS;
    float* Qs = Vs + 127 * RS;
    float* Pt = Qs + TQ * RS;

    const int t0 = blockIdx.x * TQ;
    const int h = blockIdx.y;
    const int tid = threadIdx.x;
    const int w = tid >> 5;
    const int lane = tid & 31;

    int base = t0 - 31;
    if (base < 0) base = 0;
    if (base > LSEQ - KV) base = LSEQ - KV;

    const float scale = 0.17677669529663687f;

    for (int idx = tid; idx < KV * 32; idx += 256) {
        int row = idx >> 5;
        int d = idx & 31;
        size_t g = (size_t)(base + row) * C3 + CDIM + h * DH + d;
        Ks[row * RS + d] = qkv[g];
        Vs[row * RS + d] = qkv[g + CDIM];
    }
    if (tid < 32) {
        Ks[126 * RS + tid] = 0.f;
        Vs[126 * RS + tid] = 0.f;
    }
    for (int idx = tid; idx < TQ * 32; idx += 256) {
        int row = idx >> 5;
        int d = idx & 31;
        Qs[row * RS + d] = qkv[(size_t)(t0 + row) * C3 + h * DH + d] * scale;
    }
    for (int idx = tid; idx < 8 * PTROWS * PTS; idx += 256)
        Pt[idx] = 0.f;
    __syncthreads();

    const int l0 = t0 + w * 8;
    const int ws0 = win_start(l0) - base;
    const int ws7 = win_start(l0 + 7) - base;
    float* Ptw = Pt + w * PTROWS * PTS;

    #pragma unroll 1
    for (int qi = 0; qi < 8; qi++) {
        const int lq = w * 8 + qi;
        const int l = t0 + lq;
        const int ws = win_start(l) - base;

        const float4* k0p = (const float4*)&Ks[(ws + lane) * RS];
        const float4* k1p = (const float4*)&Ks[(ws + 32 + lane) * RS];
        const float4* qp  = (const float4*)&Qs[lq * RS];

        float s0 = 0.f, s1 = 0.f;
        #pragma unroll
        for (int d4 = 0; d4 < 8; d4++) {
            float4 q4 = qp[d4];
            float4 ka = k0p[d4];
            float4 kb = k1p[d4];
            s0 += q4.x * ka.x + q4.y * ka.y + q4.z * ka.z + q4.w * ka.w;
            s1 += q4.x * kb.x + q4.y * kb.y + q4.z * kb.z + q4.w * kb.w;
        }

        float m = fmaxf(s0, (lane < 31) ? s1 : -1e30f);
        #pragma unroll
        for (int o = 16; o > 0; o >>= 1)
            m = fmaxf(m, __shfl_xor_sync(0xffffffffu, m, o));
        float e0 = __expf(s0 - m);
        float e1 = (lane < 31) ? __expf(s1 - m) : 0.f;
        float sum = e0 + e1;
        #pragma unroll
        for (int o = 16; o > 0; o >>= 1)
            sum += __shfl_xor_sync(0xffffffffu, sum, o);
        float inv = __frcp_rn(sum);

        const int off = ws - ws0;
        Ptw[(off + lane) * PTS + qi]      = e0 * inv;
        Ptw[(off + 32 + lane) * PTS + qi] = e1 * inv;
    }
    __syncwarp();

    const int nU = ws7 - ws0 + 64;
    float acc[8];
    #pragma unroll
    for (int q = 0; q < 8; q++) acc[q] = 0.f;

    const float* vb = &Vs[ws0 * RS + lane];
    #pragma unroll 4
    for (int jj = 0; jj < nU; jj++) {
        float v = vb[jj * RS];
        float4 pa = *(const float4*)&Ptw[jj * PTS];
        float4 pb = *(const float4*)&Ptw[jj * PTS + 4];
        acc[0] = fmaf(pa.x, v, acc[0]);
        acc[1] = fmaf(pa.y, v, acc[1]);
        acc[2] = fmaf(pa.z, v, acc[2]);
        acc[3] = fmaf(pa.w, v, acc[3]);
        acc[4] = fmaf(pb.x, v, acc[4]);
        acc[5] = fmaf(pb.y, v, acc[5]);
        acc[6] = fmaf(pb.z, v, acc[6]);
        acc[7] = fmaf(pb.w, v, acc[7]);
    }

    #pragma unroll
    for (int q = 0; q < 8; q++)
        out[(size_t)(l0 + q) * CDIM + h * DH + lane] = round_tf32(acc[q]);
}

// ---------------------------------------------------------------------------
extern "C" void kernel_launch(void* const* d_in, const int* in_sizes, int n_in,
                              void* d_out, int out_size)
{
    const float* x    = (const float*)d_in[0];
    const float* Wp   = (const float*)d_in[1];
    const float* bp   = (const float*)d_in[2];
    const float* Wqkv = (const float*)d_in[3];
    const float* bqkv = (const float*)d_in[4];
    const float* Wo   = (const float*)d_in[5];
    const float* bo   = (const float*)d_in[6];
    float* out = (float*)d_out;

    float *p_y, *p_qkv, *p_att, *wpr, *wqr, *wor;
    cudaGetSymbolAddress((void**)&p_y,   g_y);
    cudaGetSymbolAddress((void**)&p_qkv, g_qkv);
    cudaGetSymbolAddress((void**)&p_att, g_att);
    cudaGetSymbolAddress((void**)&wpr, g_Wp_r);
    cudaGetSymbolAddress((void**)&wqr, g_Wq_r);
    cudaGetSymbolAddress((void**)&wor, g_Wo_r);

    const int natten_smem = (127 * RS * 2 + TQ * RS + 8 * PTROWS * PTS) * 4;
    static bool attr_set = false;
    if (!attr_set) {
        cudaFuncSetAttribute(natten_kernel,
                             cudaFuncAttributeMaxDynamicSharedMemorySize, natten_smem);
        cudaFuncSetAttribute(gemm_tf32_kernel<true, true>,
                             cudaFuncAttributeMaxDynamicSharedMemorySize, GSMEM);
        cudaFuncSetAttribute(gemm_tf32_kernel<false, false>,
                             cudaFuncAttributeMaxDynamicSharedMemorySize, GSMEM);
        attr_set = true;
    }

    // round weights to tf32 RNE
    prep_weights_kernel<<<(FIN * CDIM + 255) / 256, 256>>>(Wp, wpr, FIN * CDIM);
    prep_weights_kernel<<<(CDIM * C3 + 255) / 256, 256>>>(Wqkv, wqr, CDIM * C3);
    prep_weights_kernel<<<(CDIM * CDIM + 255) / 256, 256>>>(Wo, wor, CDIM * CDIM);

    // y = x @ Wp + bp   (A=x needs cvt; store y pre-rounded)
    gemm_tf32_kernel<true, true><<<dim3(CDIM / 128, LSEQ / 64), 256, GSMEM>>>(
        x, wpr, bp, p_y, LSEQ, CDIM, FIN);

    // qkv = y @ Wqkv + bqkv  (A=y pre-rounded; qkv full fp32 for attention)
    gemm_tf32_kernel<false, false><<<dim3(C3 / 128, LSEQ / 64), 256, GSMEM>>>(
        p_y, wqr, bqkv, p_qkv, LSEQ, C3, CDIM);

    natten_kernel<<<dim3(LSEQ / TQ, NH), 256, natten_smem>>>(p_qkv, p_att);

    // out = att @ Wo + bo  (A=att pre-rounded; final output full fp32)
    gemm_tf32_kernel<false, false><<<dim3(CDIM / 128, LSEQ / 64), 256, GSMEM>>>(
        p_att, wor, bo, out, LSEQ, CDIM, CDIM);
}